// round 3
// baseline (speedup 1.0000x reference)
#include <cuda_runtime.h>
#include <cuda_bf16.h>
#include <math.h>

#define BB 4
#define SS 2048
#define HH 1024
#define NHH 16
#define HDD 64

// Scratch (module-load allocated, allowed per rules)
__device__ float g_q[(size_t)BB * NHH * SS * HDD];
__device__ float g_k[(size_t)BB * NHH * SS * HDD];
__device__ float g_v[(size_t)BB * NHH * SS * HDD];
__device__ float g_ctx[(size_t)BB * SS * HH];

// ---------------------------------------------------------------------------
// SGEMM: C[M=8192, N=1024] = X[8192,1024] * W[1024,1024] + bias
// 128x128 block tile, KC=16, 256 threads, 8x8 register tile.
// transposed_layout=1: write element (m,n) to out[((b*NH+h)*S+s)*HD+d]
// ---------------------------------------------------------------------------
__global__ __launch_bounds__(256) void gemm_proj(
    const float* __restrict__ X, const float* __restrict__ W,
    const float* __restrict__ bias, float* __restrict__ out,
    int transposed_layout)
{
    __shared__ float As[16][132];   // A stored transposed: As[k][m]
    __shared__ float Bs[16][132];   // Bs[k][n]

    const int bm = blockIdx.y * 128;
    const int bn = blockIdx.x * 128;
    const int t  = threadIdx.x;

    const int tm = (t % 16) * 8;
    const int tn = (t / 16) * 8;

    float acc[8][8];
#pragma unroll
    for (int i = 0; i < 8; i++)
#pragma unroll
        for (int j = 0; j < 8; j++) acc[i][j] = 0.f;

    for (int k0 = 0; k0 < HH; k0 += 16) {
        // Load A tile 128(m) x 16(k) -> As[k][m]
#pragma unroll
        for (int i = 0; i < 2; i++) {
            int idx = t + i * 256;          // 512 float4 units
            int m   = idx >> 2;             // 0..127
            int kq  = (idx & 3) * 4;        // 0,4,8,12
            float4 a = *(const float4*)&X[(size_t)(bm + m) * HH + k0 + kq];
            As[kq + 0][m] = a.x; As[kq + 1][m] = a.y;
            As[kq + 2][m] = a.z; As[kq + 3][m] = a.w;
        }
        // Load B tile 16(k) x 128(n) -> Bs[k][n]
#pragma unroll
        for (int i = 0; i < 2; i++) {
            int idx = t + i * 256;
            int kk  = idx >> 5;             // 0..15
            int nq  = (idx & 31) * 4;       // 0..124
            float4 b = *(const float4*)&W[(size_t)(k0 + kk) * HH + bn + nq];
            *(float4*)&Bs[kk][nq] = b;
        }
        __syncthreads();
#pragma unroll
        for (int kk = 0; kk < 16; kk++) {
            float a[8], b[8];
#pragma unroll
            for (int j = 0; j < 4; j++) {
                ((float4*)a)[j >> 1] = ((float4*)a)[j >> 1]; // no-op keep compiler calm
            }
#pragma unroll
            for (int j = 0; j < 8; j++) { a[j] = As[kk][tm + j]; b[j] = Bs[kk][tn + j]; }
#pragma unroll
            for (int i = 0; i < 8; i++)
#pragma unroll
                for (int j = 0; j < 8; j++)
                    acc[i][j] += a[i] * b[j];
        }
        __syncthreads();
    }

#pragma unroll
    for (int i = 0; i < 8; i++) {
        int m = bm + tm + i;
#pragma unroll
        for (int j = 0; j < 8; j++) {
            int n = bn + tn + j;
            float v = acc[i][j] + bias[n];
            if (!transposed_layout) {
                out[(size_t)m * HH + n] = v;
            } else {
                int b_ = m / SS, s_ = m % SS;
                int h_ = n / HDD, d_ = n % HDD;
                out[(((size_t)b_ * NHH + h_) * SS + s_) * HDD + d_] = v;
            }
        }
    }
}

// ---------------------------------------------------------------------------
// Fused attention: one CTA per (b,h, 16-row q tile).
// Phase 1: scores tile 16 x 2048 into SMEM (Q·K^T / sqrt(HD), masked)
// Phase 2: softmax in SMEM, write normalized probs to global attn
// Phase 3: ctx = P · V accumulated from SMEM probs
// ---------------------------------------------------------------------------
#define TQ 16
#define KC 128

__global__ __launch_bounds__(256) void attn_kernel(
    const int* __restrict__ mask,
    float* __restrict__ attn_out,   // [B, NH, S, S]
    float* __restrict__ ctx)        // [B, S, H]
{
    extern __shared__ float smem[];
    float* sc = smem;                       // TQ * SS       (scores/probs)
    float* ch = smem + TQ * SS;             // KC * 68       (K or V chunk)
    float* qs = ch + KC * 68;               // TQ * 65       (Q tile)

    const int bh = blockIdx.y;              // 0..63
    const int b  = bh / NHH;
    const int h  = bh % NHH;
    const int q0 = blockIdx.x * TQ;

    const float* qb = g_q + (size_t)bh * SS * HDD;
    const float* kb = g_k + (size_t)bh * SS * HDD;
    const float* vb = g_v + (size_t)bh * SS * HDD;

    const int t    = threadIdx.x;
    const int warp = t >> 5;
    const int lane = t & 31;

    // Load Q tile (16 x 64), stride 65
    for (int i = t; i < TQ * HDD; i += 256) {
        int r = i / HDD, d = i % HDD;
        qs[r * 65 + d] = qb[(size_t)(q0 + r) * HDD + d];
    }
    __syncthreads();

    // ---- Phase 1: scores ----
    const int qr = warp * 2;
    for (int kc = 0; kc < SS; kc += KC) {
        // load K chunk KC x 64 -> ch stride 65
        for (int i = t; i < KC * 16; i += 256) {
            int r = i >> 4, c4 = (i & 15) * 4;
            float4 kv = *(const float4*)&kb[(size_t)(kc + r) * HDD + c4];
            ch[r * 65 + c4 + 0] = kv.x; ch[r * 65 + c4 + 1] = kv.y;
            ch[r * 65 + c4 + 2] = kv.z; ch[r * 65 + c4 + 3] = kv.w;
        }
        __syncthreads();

        float acc0[4] = {0.f, 0.f, 0.f, 0.f};
        float acc1[4] = {0.f, 0.f, 0.f, 0.f};
#pragma unroll 8
        for (int d = 0; d < HDD; d++) {
            float q0v = qs[qr * 65 + d];
            float q1v = qs[(qr + 1) * 65 + d];
#pragma unroll
            for (int j = 0; j < 4; j++) {
                float kv = ch[(lane + 32 * j) * 65 + d];
                acc0[j] += q0v * kv;
                acc1[j] += q1v * kv;
            }
        }
        const float inv = 0.125f; // 1/sqrt(64)
#pragma unroll
        for (int j = 0; j < 4; j++) {
            int col = kc + lane + 32 * j;
            int mv = mask[(size_t)b * SS + col];
            float s0 = (mv == 0) ? -1e9f : acc0[j] * inv;
            float s1 = (mv == 0) ? -1e9f : acc1[j] * inv;
            sc[(size_t)qr * SS + col]       = s0;
            sc[(size_t)(qr + 1) * SS + col] = s1;
        }
        __syncthreads();
    }

    // ---- Phase 2: softmax (each warp owns the 2 rows it computed) ----
#pragma unroll
    for (int rr = 0; rr < 2; rr++) {
        int r = warp * 2 + rr;
        float* row = sc + (size_t)r * SS;
        float mx = -INFINITY;
        for (int c = lane; c < SS; c += 32) mx = fmaxf(mx, row[c]);
#pragma unroll
        for (int o = 16; o; o >>= 1) mx = fmaxf(mx, __shfl_xor_sync(0xffffffffu, mx, o));
        float sum = 0.f;
        for (int c = lane; c < SS; c += 32) {
            float e = expf(row[c] - mx);
            row[c] = e;
            sum += e;
        }
#pragma unroll
        for (int o = 16; o; o >>= 1) sum += __shfl_xor_sync(0xffffffffu, sum, o);
        float rcp = 1.f / sum;
        float* gout = attn_out + ((size_t)bh * SS + (q0 + r)) * SS;
        for (int c = lane; c < SS; c += 32) {
            float p = row[c] * rcp;
            row[c] = p;
            gout[c] = p;     // coalesced
        }
    }
    __syncthreads();

    // ---- Phase 3: ctx = P · V ----
    const int pr = t / 16;          // 0..15 q row
    const int dc = (t % 16) * 4;    // 0..60 head-dim col
    float acc[4] = {0.f, 0.f, 0.f, 0.f};
    for (int kc = 0; kc < SS; kc += KC) {
        // load V chunk KC x 64 -> ch stride 68 (float4 friendly)
        for (int i = t; i < KC * 16; i += 256) {
            int r = i >> 4, c4 = (i & 15) * 4;
            *(float4*)&ch[r * 68 + c4] = *(const float4*)&vb[(size_t)(kc + r) * HDD + c4];
        }
        __syncthreads();
#pragma unroll 8
        for (int kk = 0; kk < KC; kk++) {
            float p = sc[(size_t)pr * SS + kc + kk];
            float4 vv = *(const float4*)&ch[kk * 68 + dc];
            acc[0] += p * vv.x; acc[1] += p * vv.y;
            acc[2] += p * vv.z; acc[3] += p * vv.w;
        }
        __syncthreads();
    }
    float4 r4 = make_float4(acc[0], acc[1], acc[2], acc[3]);
    *(float4*)&ctx[((size_t)b * SS + q0 + pr) * HH + h * HDD + dc] = r4;
}

// ---------------------------------------------------------------------------

extern "C" void kernel_launch(void* const* d_in, const int* in_sizes, int n_in,
                              void* d_out, int out_size)
{
    const float* hs   = (const float*)d_in[0];
    const int*   mask = (const int*)d_in[1];
    const float* Wq   = (const float*)d_in[2];
    const float* bq   = (const float*)d_in[3];
    const float* Wk   = (const float*)d_in[4];
    const float* bk   = (const float*)d_in[5];
    const float* Wv   = (const float*)d_in[6];
    const float* bv   = (const float*)d_in[7];
    const float* Wo   = (const float*)d_in[8];
    const float* bo   = (const float*)d_in[9];

    float* out  = (float*)d_out;                       // [B,S,H]
    float* attn = out + (size_t)BB * SS * HH;          // [B,NH,S,S]

    float *gq, *gk, *gv, *gctx;
    cudaGetSymbolAddress((void**)&gq,   g_q);
    cudaGetSymbolAddress((void**)&gk,   g_k);
    cudaGetSymbolAddress((void**)&gv,   g_v);
    cudaGetSymbolAddress((void**)&gctx, g_ctx);

    dim3 gblock(256);
    dim3 ggrid(HH / 128, (BB * SS) / 128);   // (8, 64)

    gemm_proj<<<ggrid, gblock>>>(hs, Wq, bq, gq, 1);
    gemm_proj<<<ggrid, gblock>>>(hs, Wk, bk, gk, 1);
    gemm_proj<<<ggrid, gblock>>>(hs, Wv, bv, gv, 1);

    size_t smem_bytes = (size_t)(TQ * SS + KC * 68 + TQ * 65) * sizeof(float); // ~166 KB
    cudaFuncSetAttribute(attn_kernel, cudaFuncAttributeMaxDynamicSharedMemorySize,
                         (int)smem_bytes);
    dim3 agrid(SS / TQ, BB * NHH);           // (128, 64)
    attn_kernel<<<agrid, 256, smem_bytes>>>(mask, attn, gctx);

    gemm_proj<<<ggrid, gblock>>>(gctx, Wo, bo, out, 0);
}

// round 4
// speedup vs baseline: 2.9663x; 2.9663x over previous
#include <cuda_runtime.h>
#include <cuda_bf16.h>
#include <math.h>

#define BB 4
#define SS 2048
#define HH 1024
#define NHH 16
#define HDD 64

// Scratch (module-load allocated, allowed per rules)
__device__ float g_q[(size_t)BB * NHH * SS * HDD];   // [bh][s][d]
__device__ float g_k[(size_t)BB * NHH * SS * HDD];   // stored TRANSPOSED: [bh][d][s]
__device__ float g_v[(size_t)BB * NHH * SS * HDD];   // [bh][s][d]
__device__ float g_ctx[(size_t)BB * SS * HH];

// ---------------------------------------------------------------------------
// SGEMM: C[M=8192, N=1024] = X[8192,1024] * W[1024,1024] + bias
// mode 0: out[m][n] row-major
// mode 1: out[((b*NH+h)*S+s)*HD+d]        ([bh][s][d])
// mode 2: out[((b*NH+h)*HD+d)*S+s]        ([bh][d][s]  = transposed, for K)
// ---------------------------------------------------------------------------
__global__ __launch_bounds__(256) void gemm_proj(
    const float* __restrict__ X, const float* __restrict__ W,
    const float* __restrict__ bias, float* __restrict__ out,
    int mode)
{
    __shared__ float As[16][132];   // A stored transposed: As[k][m]
    __shared__ float Bs[16][132];   // Bs[k][n]

    const int bm = blockIdx.y * 128;
    const int bn = blockIdx.x * 128;
    const int t  = threadIdx.x;

    const int tm = (t % 16) * 8;
    const int tn = (t / 16) * 8;

    float acc[8][8];
#pragma unroll
    for (int i = 0; i < 8; i++)
#pragma unroll
        for (int j = 0; j < 8; j++) acc[i][j] = 0.f;

    for (int k0 = 0; k0 < HH; k0 += 16) {
#pragma unroll
        for (int i = 0; i < 2; i++) {
            int idx = t + i * 256;
            int m   = idx >> 2;
            int kq  = (idx & 3) * 4;
            float4 a = *(const float4*)&X[(size_t)(bm + m) * HH + k0 + kq];
            As[kq + 0][m] = a.x; As[kq + 1][m] = a.y;
            As[kq + 2][m] = a.z; As[kq + 3][m] = a.w;
        }
#pragma unroll
        for (int i = 0; i < 2; i++) {
            int idx = t + i * 256;
            int kk  = idx >> 5;
            int nq  = (idx & 31) * 4;
            float4 b = *(const float4*)&W[(size_t)(k0 + kk) * HH + bn + nq];
            *(float4*)&Bs[kk][nq] = b;
        }
        __syncthreads();
#pragma unroll
        for (int kk = 0; kk < 16; kk++) {
            float a[8], b[8];
#pragma unroll
            for (int j = 0; j < 8; j++) { a[j] = As[kk][tm + j]; b[j] = Bs[kk][tn + j]; }
#pragma unroll
            for (int i = 0; i < 8; i++)
#pragma unroll
                for (int j = 0; j < 8; j++)
                    acc[i][j] += a[i] * b[j];
        }
        __syncthreads();
    }

#pragma unroll
    for (int i = 0; i < 8; i++) {
        int m = bm + tm + i;
#pragma unroll
        for (int j = 0; j < 8; j++) {
            int n = bn + tn + j;
            float v = acc[i][j] + bias[n];
            if (mode == 0) {
                out[(size_t)m * HH + n] = v;
            } else {
                int b_ = m / SS, s_ = m % SS;
                int h_ = n / HDD, d_ = n % HDD;
                if (mode == 1)
                    out[(((size_t)b_ * NHH + h_) * SS + s_) * HDD + d_] = v;
                else
                    out[(((size_t)b_ * NHH + h_) * HDD + d_) * SS + s_] = v;
            }
        }
    }
}

// ---------------------------------------------------------------------------
// Fused attention, register-tiled microkernels.
// One CTA per (b,h, 16-row q tile). 256 threads.
// SMEM layout (floats):
//   sc : [2048][17]  scores / probs, stored TRANSPOSED sc[col][q]  (34816)
//   As : [64][20]    Q^T tile As[d][q]                              (1280)
//   Bs : 17408       double-buffered K^T / V slabs, reused as reduce buffer
// Total 53504 floats = 214016 bytes.
// ---------------------------------------------------------------------------
#define TQ   16
#define SCP  17
#define ASP  20
#define BSP  1032   // 1024 + 8 pad
#define VBP  68     // 64 + 4 pad
#define SC_FLOATS   (SS * SCP)        // 34816
#define AS_FLOATS   (64 * ASP)        // 1280
#define BS_HALF     (8 * BSP)         // 8256 (8 d-rows x 1024 cols)
#define VB_HALF     (128 * VBP)       // 8704 (128 k-rows x 64 d)
#define BS_FLOATS   17408
#define SMEM_FLOATS (SC_FLOATS + AS_FLOATS + BS_FLOATS)

__global__ __launch_bounds__(256) void attn_kernel(
    const int* __restrict__ mask,
    float* __restrict__ attn_out,   // [B, NH, S, S]
    float* __restrict__ ctx)        // [B, S, H]
{
    extern __shared__ float smem[];
    float* sc = smem;
    float* As = smem + SC_FLOATS;
    float* Bs = As + AS_FLOATS;

    const int bh = blockIdx.y;
    const int b  = bh / NHH;
    const int h  = bh % NHH;
    const int q0 = blockIdx.x * TQ;

    const float* qb = g_q + (size_t)bh * SS * HDD;
    const float* kT = g_k + (size_t)bh * HDD * SS;   // [d][s]
    const float* vb = g_v + (size_t)bh * SS * HDD;

    const int t    = threadIdx.x;
    const int warp = t >> 5;
    const int lane = t & 31;

    // ---- Load Q tile transposed into As[d][q] ----
    for (int idx = t; idx < TQ * HDD; idx += 256) {
        int q = idx >> 6, d = idx & 63;
        As[d * ASP + q] = qb[(size_t)(q0 + q) * HDD + d];
    }

    // ================= Phase 1: scores =================
    // Thread tile: 8 q-rows x 8 cols.  qg = t&1 (q block), cg = t>>1 (col block)
    {
        const int qg = (t & 1) * 8;
        const int cg = (t >> 1) * 8;
        float4 pre[8];

        for (int pass = 0; pass < 2; pass++) {
            const float* kTp = kT + pass * 1024;
            float acc[8][8];
#pragma unroll
            for (int i = 0; i < 8; i++)
#pragma unroll
                for (int j = 0; j < 8; j++) acc[i][j] = 0.f;

            // prologue: slab 0 (d rows 0..7)
#pragma unroll
            for (int i = 0; i < 8; i++) {
                int idx = t + i * 256; int row = idx >> 8; int c4 = (idx & 255) * 4;
                pre[i] = *(const float4*)&kTp[(size_t)row * SS + c4];
            }
            if (pass == 0) { /* ensure As visible before first compute */ }
#pragma unroll
            for (int i = 0; i < 8; i++) {
                int idx = t + i * 256; int row = idx >> 8; int c4 = (idx & 255) * 4;
                *(float4*)&Bs[row * BSP + c4] = pre[i];
            }
            __syncthreads();

            for (int s = 0; s < 8; s++) {
                const int d0 = s * 8;
                if (s < 7) {
#pragma unroll
                    for (int i = 0; i < 8; i++) {
                        int idx = t + i * 256; int row = idx >> 8; int c4 = (idx & 255) * 4;
                        pre[i] = *(const float4*)&kTp[(size_t)(d0 + 8 + row) * SS + c4];
                    }
                }
                const float* buf = Bs + (s & 1) * BS_HALF;
#pragma unroll
                for (int dd = 0; dd < 8; dd++) {
                    float a[8], bv[8];
                    *(float4*)&a[0]  = *(float4*)&As[(d0 + dd) * ASP + qg];
                    *(float4*)&a[4]  = *(float4*)&As[(d0 + dd) * ASP + qg + 4];
                    *(float4*)&bv[0] = *(const float4*)&buf[dd * BSP + cg];
                    *(float4*)&bv[4] = *(const float4*)&buf[dd * BSP + cg + 4];
#pragma unroll
                    for (int i = 0; i < 8; i++)
#pragma unroll
                        for (int j = 0; j < 8; j++)
                            acc[i][j] += a[i] * bv[j];
                }
                if (s < 7) {
                    float* nb = Bs + ((s + 1) & 1) * BS_HALF;
#pragma unroll
                    for (int i = 0; i < 8; i++) {
                        int idx = t + i * 256; int row = idx >> 8; int c4 = (idx & 255) * 4;
                        *(float4*)&nb[row * BSP + c4] = pre[i];
                    }
                }
                __syncthreads();
            }

            // epilogue: mask + scale, store transposed sc[col][q]
#pragma unroll
            for (int j = 0; j < 8; j++) {
                int col = pass * 1024 + cg + j;
                int mv  = mask[(size_t)b * SS + col];
#pragma unroll
                for (int i = 0; i < 8; i++) {
                    float v = (mv == 0) ? -1e9f : acc[i][j] * 0.125f;
                    sc[col * SCP + qg + i] = v;
                }
            }
        }
    }
    __syncthreads();

    // ================= Phase 2: softmax =================
#pragma unroll
    for (int rr = 0; rr < 2; rr++) {
        int r = warp * 2 + rr;
        float mx = -INFINITY;
        for (int c = lane; c < SS; c += 32) mx = fmaxf(mx, sc[c * SCP + r]);
#pragma unroll
        for (int o = 16; o; o >>= 1) mx = fmaxf(mx, __shfl_xor_sync(0xffffffffu, mx, o));
        float sum = 0.f;
        for (int c = lane; c < SS; c += 32) {
            float e = expf(sc[c * SCP + r] - mx);
            sc[c * SCP + r] = e;
            sum += e;
        }
#pragma unroll
        for (int o = 16; o; o >>= 1) sum += __shfl_xor_sync(0xffffffffu, sum, o);
        float rcp = 1.f / sum;
        float* gout = attn_out + ((size_t)bh * SS + (q0 + r)) * SS;
        for (int c = lane; c < SS; c += 32) {
            float p = sc[c * SCP + r] * rcp;
            sc[c * SCP + r] = p;
            gout[c] = p;
        }
    }
    __syncthreads();

    // ================= Phase 3: ctx = P * V =================
    // 16 k-groups (kg = t>>4), within group 8q x 8d register tile.
    {
        const int kg  = t >> 4;
        const int qg  = ((t >> 3) & 1) * 8;
        const int dg  = (t & 7) * 8;
        float acc[8][8];
#pragma unroll
        for (int i = 0; i < 8; i++)
#pragma unroll
            for (int j = 0; j < 8; j++) acc[i][j] = 0.f;

        float4 pre[8];
        // prologue: V slab 0 (k rows 0..127)
#pragma unroll
        for (int i = 0; i < 8; i++) {
            int idx = t + i * 256; int row = idx >> 4; int c4 = (idx & 15) * 4;
            pre[i] = *(const float4*)&vb[(size_t)row * HDD + c4];
        }
#pragma unroll
        for (int i = 0; i < 8; i++) {
            int idx = t + i * 256; int row = idx >> 4; int c4 = (idx & 15) * 4;
            *(float4*)&Bs[row * VBP + c4] = pre[i];
        }
        __syncthreads();

        for (int s = 0; s < 16; s++) {
            const int ks = s * 128;
            if (s < 15) {
#pragma unroll
                for (int i = 0; i < 8; i++) {
                    int idx = t + i * 256; int row = idx >> 4; int c4 = (idx & 15) * 4;
                    pre[i] = *(const float4*)&vb[(size_t)(ks + 128 + row) * HDD + c4];
                }
            }
            const float* buf = Bs + (s & 1) * VB_HALF;
#pragma unroll
            for (int kk = 0; kk < 8; kk++) {
                const int kl = kg * 8 + kk;
                const int k  = ks + kl;
                float a[8], bv[8];
#pragma unroll
                for (int i = 0; i < 8; i++) a[i] = sc[k * SCP + qg + i];
                *(float4*)&bv[0] = *(const float4*)&buf[kl * VBP + dg];
                *(float4*)&bv[4] = *(const float4*)&buf[kl * VBP + dg + 4];
#pragma unroll
                for (int i = 0; i < 8; i++)
#pragma unroll
                    for (int j = 0; j < 8; j++)
                        acc[i][j] += a[i] * bv[j];
            }
            if (s < 15) {
                float* nb = Bs + ((s + 1) & 1) * VB_HALF;
#pragma unroll
                for (int i = 0; i < 8; i++) {
                    int idx = t + i * 256; int row = idx >> 4; int c4 = (idx & 15) * 4;
                    *(float4*)&nb[row * VBP + c4] = pre[i];
                }
            }
            __syncthreads();
        }

        // reduction over the 16 k-groups, staged in Bs (16 x 1024 floats)
        float* red = Bs;
#pragma unroll
        for (int i = 0; i < 8; i++)
#pragma unroll
            for (int j = 0; j < 8; j++)
                red[kg * 1024 + (qg + i) * 64 + dg + j] = acc[i][j];
        __syncthreads();

        const int oid = t * 4;
        float4 sm = make_float4(0.f, 0.f, 0.f, 0.f);
#pragma unroll
        for (int g = 0; g < 16; g++) {
            float4 v = *(const float4*)&red[g * 1024 + oid];
            sm.x += v.x; sm.y += v.y; sm.z += v.z; sm.w += v.w;
        }
        const int q = oid >> 6, d = oid & 63;
        *(float4*)&ctx[((size_t)b * SS + q0 + q) * HH + h * HDD + d] = sm;
    }
}

// ---------------------------------------------------------------------------

extern "C" void kernel_launch(void* const* d_in, const int* in_sizes, int n_in,
                              void* d_out, int out_size)
{
    const float* hs   = (const float*)d_in[0];
    const int*   mask = (const int*)d_in[1];
    const float* Wq   = (const float*)d_in[2];
    const float* bq   = (const float*)d_in[3];
    const float* Wk   = (const float*)d_in[4];
    const float* bk   = (const float*)d_in[5];
    const float* Wv   = (const float*)d_in[6];
    const float* bv   = (const float*)d_in[7];
    const float* Wo   = (const float*)d_in[8];
    const float* bo   = (const float*)d_in[9];

    float* out  = (float*)d_out;                       // [B,S,H]
    float* attn = out + (size_t)BB * SS * HH;          // [B,NH,S,S]

    float *gq, *gk, *gv, *gctx;
    cudaGetSymbolAddress((void**)&gq,   g_q);
    cudaGetSymbolAddress((void**)&gk,   g_k);
    cudaGetSymbolAddress((void**)&gv,   g_v);
    cudaGetSymbolAddress((void**)&gctx, g_ctx);

    dim3 gblock(256);
    dim3 ggrid(HH / 128, (BB * SS) / 128);   // (8, 64)

    gemm_proj<<<ggrid, gblock>>>(hs, Wq, bq, gq, 1);
    gemm_proj<<<ggrid, gblock>>>(hs, Wk, bk, gk, 2);   // K transposed [bh][d][s]
    gemm_proj<<<ggrid, gblock>>>(hs, Wv, bv, gv, 1);

    size_t smem_bytes = (size_t)SMEM_FLOATS * sizeof(float); // 214016 B
    cudaFuncSetAttribute(attn_kernel, cudaFuncAttributeMaxDynamicSharedMemorySize,
                         (int)smem_bytes);
    dim3 agrid(SS / TQ, BB * NHH);           // (128, 64)
    attn_kernel<<<agrid, 256, smem_bytes>>>(mask, attn, gctx);

    gemm_proj<<<ggrid, gblock>>>(gctx, Wo, bo, out, 0);
}

// round 6
// speedup vs baseline: 3.7192x; 1.2538x over previous
#include <cuda_runtime.h>
#include <cuda_bf16.h>
#include <math.h>
#include <stdint.h>

#define BB 4
#define SS 2048
#define HH 1024
#define NHH 16
#define HDD 64

// ---------------------------------------------------------------------------
// Scratch
// ---------------------------------------------------------------------------
__device__ float g_q[(size_t)BB * NHH * SS * HDD];   // [bh][s][d]
__device__ float g_k[(size_t)BB * NHH * SS * HDD];   // TRANSPOSED: [bh][d][s]
__device__ float g_v[(size_t)BB * NHH * SS * HDD];   // [bh][s][d]
__device__ float g_ctx[(size_t)BB * SS * HH];

__device__ __nv_bfloat16 g_xhi[(size_t)BB * SS * HH];  // activation hi
__device__ __nv_bfloat16 g_xlo[(size_t)BB * SS * HH];  // activation lo
__device__ __nv_bfloat16 g_whi[(size_t)HH * HH];       // weight^T hi [n][k]
__device__ __nv_bfloat16 g_wlo[(size_t)HH * HH];       // weight^T lo [n][k]

// ---------------------------------------------------------------------------
// Split fp32 -> bf16 hi/lo (vectorized by 4)
// ---------------------------------------------------------------------------
__global__ __launch_bounds__(256) void split_kernel(
    const float* __restrict__ x, __nv_bfloat16* __restrict__ hi,
    __nv_bfloat16* __restrict__ lo, int n4)
{
    int i = blockIdx.x * 256 + threadIdx.x;
    if (i >= n4) return;
    float4 v = ((const float4*)x)[i];
    __nv_bfloat16 h0 = __float2bfloat16(v.x), h1 = __float2bfloat16(v.y);
    __nv_bfloat16 h2 = __float2bfloat16(v.z), h3 = __float2bfloat16(v.w);
    __nv_bfloat16 l0 = __float2bfloat16(v.x - __bfloat162float(h0));
    __nv_bfloat16 l1 = __float2bfloat16(v.y - __bfloat162float(h1));
    __nv_bfloat16 l2 = __float2bfloat16(v.z - __bfloat162float(h2));
    __nv_bfloat16 l3 = __float2bfloat16(v.w - __bfloat162float(h3));
    ushort4 hv, lv;
    hv.x = *(unsigned short*)&h0; hv.y = *(unsigned short*)&h1;
    hv.z = *(unsigned short*)&h2; hv.w = *(unsigned short*)&h3;
    lv.x = *(unsigned short*)&l0; lv.y = *(unsigned short*)&l1;
    lv.z = *(unsigned short*)&l2; lv.w = *(unsigned short*)&l3;
    ((ushort4*)hi)[i] = hv;
    ((ushort4*)lo)[i] = lv;
}

// ---------------------------------------------------------------------------
// Split + transpose for weights: out[n][k] = split(W[k][n]),  1024x1024
// ---------------------------------------------------------------------------
__global__ __launch_bounds__(256) void split_transpose_kernel(
    const float* __restrict__ W, __nv_bfloat16* __restrict__ hi,
    __nv_bfloat16* __restrict__ lo)
{
    __shared__ float tile[32][33];
    const int k0 = blockIdx.y * 32;
    const int n0 = blockIdx.x * 32;
    const int tx = threadIdx.x & 31, ty = threadIdx.x >> 5;  // 32 x 8
#pragma unroll
    for (int i = 0; i < 4; i++)
        tile[ty + i * 8][tx] = W[(size_t)(k0 + ty + i * 8) * HH + n0 + tx];
    __syncthreads();
#pragma unroll
    for (int i = 0; i < 4; i++) {
        int n = ty + i * 8, k = tx;
        float v = tile[k][n];
        __nv_bfloat16 h = __float2bfloat16(v);
        __nv_bfloat16 l = __float2bfloat16(v - __bfloat162float(h));
        hi[(size_t)(n0 + n) * HH + k0 + k] = h;
        lo[(size_t)(n0 + n) * HH + k0 + k] = l;
    }
}

// ---------------------------------------------------------------------------
// mma.sync helpers
// ---------------------------------------------------------------------------
__device__ __forceinline__ uint32_t smem_u32(const void* p) {
    uint32_t a;
    asm("{ .reg .u64 t; cvta.to.shared.u64 t, %1; cvt.u32.u64 %0, t; }" : "=r"(a) : "l"(p));
    return a;
}
__device__ __forceinline__ void ldmx4(uint32_t* r, uint32_t addr) {
    asm volatile("ldmatrix.sync.aligned.m8n8.x4.shared.b16 {%0,%1,%2,%3}, [%4];"
                 : "=r"(r[0]), "=r"(r[1]), "=r"(r[2]), "=r"(r[3]) : "r"(addr));
}
__device__ __forceinline__ void mma16816(float* c, const uint32_t* a,
                                         uint32_t b0, uint32_t b1) {
    asm volatile("mma.sync.aligned.m16n8k16.row.col.f32.bf16.bf16.f32 "
                 "{%0,%1,%2,%3}, {%4,%5,%6,%7}, {%8,%9}, {%0,%1,%2,%3};"
                 : "+f"(c[0]), "+f"(c[1]), "+f"(c[2]), "+f"(c[3])
                 : "r"(a[0]), "r"(a[1]), "r"(a[2]), "r"(a[3]), "r"(b0), "r"(b1));
}

// ---------------------------------------------------------------------------
// Tensor-core GEMM via mma.sync: C[8192,1024] = X·W + bias  (bf16 split, 3 passes)
// CTA tile 128x128, 8 warps (2m x 4n), warp tile 64x32, BK=32 double-buffered.
// mode 0: row-major;  mode 1: [bh][s][d];  mode 2: [bh][d][s]
// ---------------------------------------------------------------------------
#define LDP 40   // smem row pitch in bf16 elems (32 + 8 pad -> conflict-free ldmatrix)

__global__ __launch_bounds__(256) void mm_mma(
    const __nv_bfloat16* __restrict__ xhi, const __nv_bfloat16* __restrict__ xlo,
    const __nv_bfloat16* __restrict__ whi, const __nv_bfloat16* __restrict__ wlo,
    const float* __restrict__ bias, float* __restrict__ out, int mode)
{
    __shared__ __nv_bfloat16 Asm[2][128 * LDP];
    __shared__ __nv_bfloat16 Bsm[2][128 * LDP];

    const int t    = threadIdx.x;
    const int wid  = t >> 5;
    const int lane = t & 31;
    const int bm   = blockIdx.y * 128;
    const int bn   = blockIdx.x * 128;
    const int wm   = (wid & 1) * 64;
    const int wn   = (wid >> 1) * 32;

    float acc[4][4][4];
#pragma unroll
    for (int i = 0; i < 4; i++)
#pragma unroll
        for (int j = 0; j < 4; j++)
#pragma unroll
            for (int r = 0; r < 4; r++) acc[i][j][r] = 0.f;

    // per-thread staging addresses: 512 uint4 per operand per chunk, 2 per thread
    const int r0 = t >> 2;             // rows t/4 and t/4+64
    const int o0 = (t & 3) * 8;        // bf16 offset within row (8 elems = 16B)

    uint4 pa[2], pb[2];

    auto ldgc = [&](int c) {
        const int p  = c >> 5;                  // 0: hi*hi, 1: lo*hi, 2: hi*lo
        const int k0 = (c & 31) * 32;
        const __nv_bfloat16* Ap = (p == 1) ? xlo : xhi;
        const __nv_bfloat16* Bp = (p == 2) ? wlo : whi;
#pragma unroll
        for (int i = 0; i < 2; i++) {
            int row = r0 + i * 64;
            pa[i] = *(const uint4*)(Ap + (size_t)(bm + row) * HH + k0 + o0);
            pb[i] = *(const uint4*)(Bp + (size_t)(bn + row) * HH + k0 + o0);
        }
    };
    auto stsc = [&](int buf) {
#pragma unroll
        for (int i = 0; i < 2; i++) {
            int row = r0 + i * 64;
            *(uint4*)&Asm[buf][row * LDP + o0] = pa[i];
            *(uint4*)&Bsm[buf][row * LDP + o0] = pb[i];
        }
    };

    ldgc(0);
    stsc(0);
    __syncthreads();

    const int lrow = lane & 15;
    const int lcb  = (lane >> 4) * 8;

    for (int c = 0; c < 96; c++) {
        const int buf = c & 1;
        if (c < 95) ldgc(c + 1);

#pragma unroll
        for (int ks = 0; ks < 2; ks++) {
            uint32_t af[4][4], bf_[2][4];
#pragma unroll
            for (int mf = 0; mf < 4; mf++)
                ldmx4(af[mf], smem_u32(&Asm[buf][(wm + mf * 16 + lrow) * LDP + ks * 16 + lcb]));
#pragma unroll
            for (int nf2 = 0; nf2 < 2; nf2++)
                ldmx4(bf_[nf2], smem_u32(&Bsm[buf][(wn + nf2 * 16 + lrow) * LDP + ks * 16 + lcb]));
#pragma unroll
            for (int mf = 0; mf < 4; mf++)
#pragma unroll
                for (int nf = 0; nf < 4; nf++) {
                    int nf2 = nf >> 1, hi = nf & 1;
                    mma16816(acc[mf][nf], af[mf], bf_[nf2][hi], bf_[nf2][2 + hi]);
                }
        }

        if (c < 95) stsc((c + 1) & 1);
        __syncthreads();
    }

    // epilogue
    const int gid = lane >> 2;       // 0..7
    const int tg  = lane & 3;        // 0..3
#pragma unroll
    for (int mf = 0; mf < 4; mf++) {
#pragma unroll
        for (int nf = 0; nf < 4; nf++) {
            int col0 = bn + wn + nf * 8 + tg * 2;
            float b0 = bias[col0], b1 = bias[col0 + 1];
#pragma unroll
            for (int half = 0; half < 2; half++) {
                int m = bm + wm + mf * 16 + gid + half * 8;
                float v0 = acc[mf][nf][half * 2 + 0] + b0;
                float v1 = acc[mf][nf][half * 2 + 1] + b1;
                if (mode == 0) {
                    out[(size_t)m * HH + col0]     = v0;
                    out[(size_t)m * HH + col0 + 1] = v1;
                } else {
                    int b_ = m / SS, s_ = m % SS;
                    int h_ = col0 / HDD, d_ = col0 % HDD;
                    if (mode == 1) {
                        float* p = &out[(((size_t)b_ * NHH + h_) * SS + s_) * HDD + d_];
                        p[0] = v0; p[1] = v1;   // d_ even, pair stays in-head (HDD=64)
                    } else {
                        float* p = &out[(((size_t)b_ * NHH + h_) * HDD + d_) * SS + s_];
                        p[0] = v0; p[SS] = v1;
                    }
                }
            }
        }
    }
}

// ---------------------------------------------------------------------------
// Fused attention (unchanged from R4 — fp32 register-tiled)
// ---------------------------------------------------------------------------
#define TQ   16
#define SCP  17
#define ASP  20
#define BSP  1032
#define VBP  68
#define SC_FLOATS   (SS * SCP)
#define AS_FLOATS   (64 * ASP)
#define BS_HALF     (8 * BSP)
#define VB_HALF     (128 * VBP)
#define BS_FLOATS   17408
#define SMEM_FLOATS (SC_FLOATS + AS_FLOATS + BS_FLOATS)

__global__ __launch_bounds__(256) void attn_kernel(
    const int* __restrict__ mask,
    float* __restrict__ attn_out,
    float* __restrict__ ctx)
{
    extern __shared__ float smemf[];
    float* sc = smemf;
    float* As = smemf + SC_FLOATS;
    float* Bs = As + AS_FLOATS;

    const int bh = blockIdx.y;
    const int b  = bh / NHH;
    const int h  = bh % NHH;
    const int q0 = blockIdx.x * TQ;

    const float* qb = g_q + (size_t)bh * SS * HDD;
    const float* kT = g_k + (size_t)bh * HDD * SS;
    const float* vb = g_v + (size_t)bh * SS * HDD;

    const int t    = threadIdx.x;
    const int warp = t >> 5;
    const int lane = t & 31;

    for (int idx = t; idx < TQ * HDD; idx += 256) {
        int q = idx >> 6, d = idx & 63;
        As[d * ASP + q] = qb[(size_t)(q0 + q) * HDD + d];
    }

    {
        const int qg = (t & 1) * 8;
        const int cg = (t >> 1) * 8;
        float4 pre[8];

        for (int pass = 0; pass < 2; pass++) {
            const float* kTp = kT + pass * 1024;
            float acc[8][8];
#pragma unroll
            for (int i = 0; i < 8; i++)
#pragma unroll
                for (int j = 0; j < 8; j++) acc[i][j] = 0.f;

#pragma unroll
            for (int i = 0; i < 8; i++) {
                int idx = t + i * 256; int row = idx >> 8; int c4 = (idx & 255) * 4;
                pre[i] = *(const float4*)&kTp[(size_t)row * SS + c4];
            }
#pragma unroll
            for (int i = 0; i < 8; i++) {
                int idx = t + i * 256; int row = idx >> 8; int c4 = (idx & 255) * 4;
                *(float4*)&Bs[row * BSP + c4] = pre[i];
            }
            __syncthreads();

            for (int s = 0; s < 8; s++) {
                const int d0 = s * 8;
                if (s < 7) {
#pragma unroll
                    for (int i = 0; i < 8; i++) {
                        int idx = t + i * 256; int row = idx >> 8; int c4 = (idx & 255) * 4;
                        pre[i] = *(const float4*)&kTp[(size_t)(d0 + 8 + row) * SS + c4];
                    }
                }
                const float* buf = Bs + (s & 1) * BS_HALF;
#pragma unroll
                for (int dd = 0; dd < 8; dd++) {
                    float a[8], bv[8];
                    *(float4*)&a[0]  = *(float4*)&As[(d0 + dd) * ASP + qg];
                    *(float4*)&a[4]  = *(float4*)&As[(d0 + dd) * ASP + qg + 4];
                    *(float4*)&bv[0] = *(const float4*)&buf[dd * BSP + cg];
                    *(float4*)&bv[4] = *(const float4*)&buf[dd * BSP + cg + 4];
#pragma unroll
                    for (int i = 0; i < 8; i++)
#pragma unroll
                        for (int j = 0; j < 8; j++)
                            acc[i][j] += a[i] * bv[j];
                }
                if (s < 7) {
                    float* nb = Bs + ((s + 1) & 1) * BS_HALF;
#pragma unroll
                    for (int i = 0; i < 8; i++) {
                        int idx = t + i * 256; int row = idx >> 8; int c4 = (idx & 255) * 4;
                        *(float4*)&nb[row * BSP + c4] = pre[i];
                    }
                }
                __syncthreads();
            }

#pragma unroll
            for (int j = 0; j < 8; j++) {
                int col = pass * 1024 + cg + j;
                int mv  = mask[(size_t)b * SS + col];
#pragma unroll
                for (int i = 0; i < 8; i++) {
                    float v = (mv == 0) ? -1e9f : acc[i][j] * 0.125f;
                    sc[col * SCP + qg + i] = v;
                }
            }
        }
    }
    __syncthreads();

#pragma unroll
    for (int rr = 0; rr < 2; rr++) {
        int r = warp * 2 + rr;
        float mx = -INFINITY;
        for (int c = lane; c < SS; c += 32) mx = fmaxf(mx, sc[c * SCP + r]);
#pragma unroll
        for (int o = 16; o; o >>= 1) mx = fmaxf(mx, __shfl_xor_sync(0xffffffffu, mx, o));
        float sum = 0.f;
        for (int c = lane; c < SS; c += 32) {
            float e = expf(sc[c * SCP + r] - mx);
            sc[c * SCP + r] = e;
            sum += e;
        }
#pragma unroll
        for (int o = 16; o; o >>= 1) sum += __shfl_xor_sync(0xffffffffu, sum, o);
        float rcp = 1.f / sum;
        float* gout = attn_out + ((size_t)bh * SS + (q0 + r)) * SS;
        for (int c = lane; c < SS; c += 32) {
            float p = sc[c * SCP + r] * rcp;
            sc[c * SCP + r] = p;
            gout[c] = p;
        }
    }
    __syncthreads();

    {
        const int kg  = t >> 4;
        const int qg  = ((t >> 3) & 1) * 8;
        const int dg  = (t & 7) * 8;
        float acc[8][8];
#pragma unroll
        for (int i = 0; i < 8; i++)
#pragma unroll
            for (int j = 0; j < 8; j++) acc[i][j] = 0.f;

        float4 pre[8];
#pragma unroll
        for (int i = 0; i < 8; i++) {
            int idx = t + i * 256; int row = idx >> 4; int c4 = (idx & 15) * 4;
            pre[i] = *(const float4*)&vb[(size_t)row * HDD + c4];
        }
#pragma unroll
        for (int i = 0; i < 8; i++) {
            int idx = t + i * 256; int row = idx >> 4; int c4 = (idx & 15) * 4;
            *(float4*)&Bs[row * VBP + c4] = pre[i];
        }
        __syncthreads();

        for (int s = 0; s < 16; s++) {
            const int ks = s * 128;
            if (s < 15) {
#pragma unroll
                for (int i = 0; i < 8; i++) {
                    int idx = t + i * 256; int row = idx >> 4; int c4 = (idx & 15) * 4;
                    pre[i] = *(const float4*)&vb[(size_t)(ks + 128 + row) * HDD + c4];
                }
            }
            const float* buf = Bs + (s & 1) * VB_HALF;
#pragma unroll
            for (int kk = 0; kk < 8; kk++) {
                const int kl = kg * 8 + kk;
                const int k  = ks + kl;
                float a[8], bv[8];
#pragma unroll
                for (int i = 0; i < 8; i++) a[i] = sc[k * SCP + qg + i];
                *(float4*)&bv[0] = *(const float4*)&buf[kl * VBP + dg];
                *(float4*)&bv[4] = *(const float4*)&buf[kl * VBP + dg + 4];
#pragma unroll
                for (int i = 0; i < 8; i++)
#pragma unroll
                    for (int j = 0; j < 8; j++)
                        acc[i][j] += a[i] * bv[j];
            }
            if (s < 15) {
                float* nb = Bs + ((s + 1) & 1) * VB_HALF;
#pragma unroll
                for (int i = 0; i < 8; i++) {
                    int idx = t + i * 256; int row = idx >> 4; int c4 = (idx & 15) * 4;
                    *(float4*)&nb[row * VBP + c4] = pre[i];
                }
            }
            __syncthreads();
        }

        float* red = Bs;
#pragma unroll
        for (int i = 0; i < 8; i++)
#pragma unroll
            for (int j = 0; j < 8; j++)
                red[kg * 1024 + (qg + i) * 64 + dg + j] = acc[i][j];
        __syncthreads();

        const int oid = t * 4;
        float4 sm = make_float4(0.f, 0.f, 0.f, 0.f);
#pragma unroll
        for (int g = 0; g < 16; g++) {
            float4 v = *(const float4*)&red[g * 1024 + oid];
            sm.x += v.x; sm.y += v.y; sm.z += v.z; sm.w += v.w;
        }
        const int q = oid >> 6, d = oid & 63;
        *(float4*)&ctx[((size_t)b * SS + q0 + q) * HH + h * HDD + d] = sm;
    }
}

// ---------------------------------------------------------------------------

extern "C" void kernel_launch(void* const* d_in, const int* in_sizes, int n_in,
                              void* d_out, int out_size)
{
    const float* hs   = (const float*)d_in[0];
    const int*   mask = (const int*)d_in[1];
    const float* Wq   = (const float*)d_in[2];
    const float* bq   = (const float*)d_in[3];
    const float* Wk   = (const float*)d_in[4];
    const float* bk   = (const float*)d_in[5];
    const float* Wv   = (const float*)d_in[6];
    const float* bv   = (const float*)d_in[7];
    const float* Wo   = (const float*)d_in[8];
    const float* bo   = (const float*)d_in[9];

    float* out  = (float*)d_out;
    float* attn = out + (size_t)BB * SS * HH;

    float *gq, *gk, *gv, *gctx;
    __nv_bfloat16 *xhi, *xlo, *whi, *wlo;
    cudaGetSymbolAddress((void**)&gq,   g_q);
    cudaGetSymbolAddress((void**)&gk,   g_k);
    cudaGetSymbolAddress((void**)&gv,   g_v);
    cudaGetSymbolAddress((void**)&gctx, g_ctx);
    cudaGetSymbolAddress((void**)&xhi,  g_xhi);
    cudaGetSymbolAddress((void**)&xlo,  g_xlo);
    cudaGetSymbolAddress((void**)&whi,  g_whi);
    cudaGetSymbolAddress((void**)&wlo,  g_wlo);

    static bool attr_done = false;
    if (!attr_done) {
        cudaFuncSetAttribute(attn_kernel, cudaFuncAttributeMaxDynamicSharedMemorySize,
                             (int)(SMEM_FLOATS * sizeof(float)));
        attr_done = true;
    }

    const int nX4 = (BB * SS * HH) / 4;
    dim3 tgrid(HH / 32, HH / 32);
    dim3 mmgrid(HH / 128, (BB * SS) / 128);   // (8, 64)

    // activation split
    split_kernel<<<(nX4 + 255) / 256, 256>>>(hs, xhi, xlo, nX4);

    // Q
    split_transpose_kernel<<<tgrid, 256>>>(Wq, whi, wlo);
    mm_mma<<<mmgrid, 256>>>(xhi, xlo, whi, wlo, bq, gq, 1);
    // K (transposed layout)
    split_transpose_kernel<<<tgrid, 256>>>(Wk, whi, wlo);
    mm_mma<<<mmgrid, 256>>>(xhi, xlo, whi, wlo, bk, gk, 2);
    // V
    split_transpose_kernel<<<tgrid, 256>>>(Wv, whi, wlo);
    mm_mma<<<mmgrid, 256>>>(xhi, xlo, whi, wlo, bv, gv, 1);

    // attention
    dim3 agrid(SS / TQ, BB * NHH);
    attn_kernel<<<agrid, 256, SMEM_FLOATS * sizeof(float)>>>(mask, attn, gctx);

    // O projection
    split_kernel<<<(nX4 + 255) / 256, 256>>>(gctx, xhi, xlo, nX4);
    split_transpose_kernel<<<tgrid, 256>>>(Wo, whi, wlo);
    mm_mma<<<mmgrid, 256>>>(xhi, xlo, whi, wlo, bo, out, 0);
}